// round 16
// baseline (speedup 1.0000x reference)
#include <cuda_runtime.h>
#include <cuda_fp16.h>
#include <math.h>
#include <stdint.h>

#define BB 8
#define CIN 512
#define COUT 1024
#define PP 2048
#define NH 8
#define DH 128

// ---------------- scratch (device globals; no allocations) ----------------
__device__ unsigned g_yh[3][BB][COUT][PP/2];    // fp16 projections (pre-BN), pairs along p
__device__ float    g_sum[3][COUT];             // batch stats accumulators
__device__ float    g_sumsq[3][COUT];
__device__ float    g_scale[3][COUT];
__device__ float    g_shift[3][COUT];
__device__ unsigned g_W[3][COUT][CIN/2];        // W rounded fp16 pairs along c
__device__ unsigned g_XT[BB][PP][CIN/2];        // x^T rounded fp16 pairs
__device__ unsigned g_Q[BB][COUT][PP/2];        // Q rounded fp16 pairs along p
__device__ unsigned g_KT[BB][NH][PP][DH/2];     // K^T rounded (pre-scaled)
__device__ unsigned g_VT[BB][NH][PP][DH/2];     // V^T rounded fp16

// log2(e) / sqrt(128): folded into K so softmax is a bare ex2
#define K_ALPHA 0.12751743f

// ---------------- helpers ----------------
__device__ __forceinline__ unsigned pack2h(float x0, float x1) {
    unsigned h;
    asm("cvt.rn.f16x2.f32 %0, %1, %2;" : "=r"(h) : "f"(x1), "f"(x0));
    return h;
}
__device__ __forceinline__ float2 unpack2h(unsigned u) {
    __half2 h = *(__half2*)&u;
    return make_float2(__half2float(__low2half(h)), __half2float(__high2half(h)));
}
__device__ __forceinline__ float fex2(float x) {
    float y;
    asm("ex2.approx.ftz.f32 %0, %1;" : "=f"(y) : "f"(x));
    return y;
}
__device__ __forceinline__ void mma16816(float* c,
    unsigned a0, unsigned a1, unsigned a2, unsigned a3, unsigned b0, unsigned b1)
{
    asm volatile(
        "mma.sync.aligned.m16n8k16.row.col.f32.f16.f16.f32 "
        "{%0,%1,%2,%3}, {%4,%5,%6,%7}, {%8,%9}, {%0,%1,%2,%3};\n"
        : "+f"(c[0]), "+f"(c[1]), "+f"(c[2]), "+f"(c[3])
        : "r"(a0), "r"(a1), "r"(a2), "r"(a3), "r"(b0), "r"(b1));
}

#define CP16(d, s) asm volatile("cp.async.cg.shared.global [%0], [%1], 16;" :: "r"(d), "l"(s) : "memory")
#define CP_COMMIT() asm volatile("cp.async.commit_group;" ::: "memory")
#define CP_WAIT(n)  asm volatile("cp.async.wait_group %0;" :: "n"(n) : "memory")
#define LDSM4(r0, r1, r2, r3, a) \
    asm volatile("ldmatrix.sync.aligned.m8n8.x4.shared.b16 {%0,%1,%2,%3}, [%4];" \
        : "=r"(r0), "=r"(r1), "=r"(r2), "=r"(r3) : "r"(a))

// ---------------- conv W -> fp16 pairs; zero stats accumulators ------------
__global__ __launch_bounds__(256) void conv_w_kernel(
    const float* __restrict__ Wq, const float* __restrict__ Wk, const float* __restrict__ Wv)
{
    int idx = blockIdx.x * 256 + threadIdx.x;
    if (idx < 3 * COUT) {
        (&g_sum[0][0])[idx] = 0.f;
        (&g_sumsq[0][0])[idx] = 0.f;
    }
    int proj = idx >> 18;
    int rem = idx & 262143;
    const float* W = (proj == 0) ? Wq : ((proj == 1) ? Wk : Wv);
    float2 v = *(const float2*)(W + (size_t)rem * 2);
    (&g_W[0][0][0])[(size_t)proj * 262144 + rem] = pack2h(v.x, v.y);
}

// ---------------- conv x -> x^T rounded fp16 pairs ----------------
__global__ __launch_bounds__(256) void conv_x_kernel(const float* __restrict__ x)
{
    __shared__ float sm[64][65];
    int p0 = blockIdx.x * 64, c0 = blockIdx.y * 64, b = blockIdx.z;
    int tid = threadIdx.x;
    for (int t = tid; t < 64 * 64; t += 256) {
        int c = t >> 6, p = t & 63;
        sm[c][p] = x[((size_t)b * CIN + c0 + c) * PP + p0 + p];
    }
    __syncthreads();
    for (int t = tid; t < 64 * 32; t += 256) {
        int p = t >> 5, cp = t & 31;
        size_t o = ((size_t)b * PP + p0 + p) * 256 + (c0 >> 1) + cp;
        (&g_XT[0][0][0])[o] = pack2h(sm[2 * cp][p], sm[2 * cp + 1][p]);
    }
}

// ---------------- Stage 1: GEMM y = W*x, fp16 store + fused stats ---------
#define G2_STR 20
#define G2_STAGE 5120
#define G2_SMEM (2 * G2_STAGE * 4)

__global__ __launch_bounds__(256, 2) void gemm1c_kernel()
{
    extern __shared__ unsigned su[];
    uint32_t smb = (uint32_t)__cvta_generic_to_shared(su);
    int z = blockIdx.z, proj = z >> 3, b = z & 7;
    int o0 = blockIdx.y * 128, p0 = blockIdx.x * 128;
    const unsigned* gW = &g_W[proj][0][0];
    const unsigned* gX = &g_XT[b][0][0];
    const int tid = threadIdx.x, w = tid >> 5, lane = tid & 31;
    const int g = lane >> 2, q = lane & 3;
    const int tt = lane >> 3, rr = lane & 7;
    const int wo = w >> 2, wp = w & 3;

    float acc[4][4][4];
#pragma unroll
    for (int i = 0; i < 4; i++)
#pragma unroll
        for (int j = 0; j < 4; j++)
#pragma unroll
            for (int e = 0; e < 4; e++) acc[i][j][e] = 0.f;

#define G2_LOAD(c) do { \
        int _s = (c) & 1, _kk = (c) * 16; \
        uint32_t _sb = smb + 4 * (_s * G2_STAGE); \
        for (int t = tid; t < 512; t += 256) { \
            int r = t >> 2, f4 = (t & 3) * 4; \
            uint32_t d = _sb + 4 * (r * G2_STR + f4); \
            CP16(d,            gW + (size_t)(o0 + r) * 256 + _kk + f4); \
            CP16(d + 4 * 2560, gX + (size_t)(p0 + r) * 256 + _kk + f4); \
        } \
    } while (0)

    G2_LOAD(0);
    CP_COMMIT();

    const int fragRow = (tt & 1) * 8 + rr;
    const int fragCol = (tt >> 1) * 4;

    for (int c = 0; c < 16; c++) {
        if (c < 15) {
            G2_LOAD(c + 1);
            CP_COMMIT();
            CP_WAIT(1);
        } else {
            CP_WAIT(0);
        }
        __syncthreads();

        const int s = c & 1;
        const uint32_t aB = smb + 4 * (s * G2_STAGE + (wo * 64 + fragRow) * G2_STR + fragCol);
        const uint32_t bB = smb + 4 * (s * G2_STAGE + 2560 + (wp * 32 + fragRow) * G2_STR + fragCol);
#pragma unroll
        for (int ks = 0; ks < 2; ks++) {
            uint32_t a[4][4];
            uint32_t bh[2][4];
#pragma unroll
            for (int nb = 0; nb < 2; nb++) {
                uint32_t ba = bB + 4 * (16 * nb * G2_STR + 8 * ks);
                LDSM4(bh[nb][0], bh[nb][1], bh[nb][2], bh[nb][3], ba);
            }
#pragma unroll
            for (int mf = 0; mf < 4; mf++) {
                uint32_t aa = aB + 4 * (16 * mf * G2_STR + 8 * ks);
                LDSM4(a[mf][0], a[mf][1], a[mf][2], a[mf][3], aa);
            }
#pragma unroll
            for (int nb = 0; nb < 2; nb++)
#pragma unroll
                for (int mf = 0; mf < 4; mf++) {
                    mma16816(acc[mf][2 * nb],     a[mf][0], a[mf][1], a[mf][2], a[mf][3], bh[nb][0], bh[nb][2]);
                    mma16816(acc[mf][2 * nb + 1], a[mf][0], a[mf][1], a[mf][2], a[mf][3], bh[nb][1], bh[nb][3]);
                }
        }
        __syncthreads();
    }

    unsigned* Yh = &g_yh[proj][b][0][0];
    const int pp2 = (p0 >> 1) + wp * 16 + q;
#pragma unroll
    for (int mf = 0; mf < 4; mf++) {
        int oo = o0 + wo * 64 + 16 * mf + g;
#pragma unroll
        for (int nf = 0; nf < 4; nf++) {
            Yh[(size_t)oo * 1024 + pp2 + 4 * nf] = pack2h(acc[mf][nf][0], acc[mf][nf][1]);
            Yh[(size_t)(oo + 8) * 1024 + pp2 + 4 * nf] = pack2h(acc[mf][nf][2], acc[mf][nf][3]);
        }
    }
#pragma unroll
    for (int mf = 0; mf < 4; mf++) {
#pragma unroll
        for (int half = 0; half < 2; half++) {
            float s = 0.f, s2 = 0.f;
#pragma unroll
            for (int nf = 0; nf < 4; nf++) {
                float v0 = acc[mf][nf][2 * half], v1 = acc[mf][nf][2 * half + 1];
                s += v0 + v1;
                s2 += v0 * v0 + v1 * v1;
            }
            s += __shfl_xor_sync(0xffffffffu, s, 1);
            s += __shfl_xor_sync(0xffffffffu, s, 2);
            s2 += __shfl_xor_sync(0xffffffffu, s2, 1);
            s2 += __shfl_xor_sync(0xffffffffu, s2, 2);
            if (q == 0) {
                int o = o0 + wo * 64 + 16 * mf + g + 8 * half;
                atomicAdd(&g_sum[proj][o], s);
                atomicAdd(&g_sumsq[proj][o], s2);
            }
        }
    }
}

// ---------------- Stage 2: finalize stats -> folded affine ----------------
__global__ __launch_bounds__(256) void finalize_stats_kernel(
    const float* __restrict__ gq, const float* __restrict__ bq,
    const float* __restrict__ gk, const float* __restrict__ bk,
    const float* __restrict__ gv, const float* __restrict__ bv)
{
    int idx = blockIdx.x * 256 + threadIdx.x;
    int proj = idx >> 10, o = idx & 1023;
    const float invn = 1.f / (BB * PP);
    float mean = g_sum[proj][o] * invn;
    float var = g_sumsq[proj][o] * invn - mean * mean;
    const float* gg = (proj == 0) ? gq : ((proj == 1) ? gk : gv);
    const float* be = (proj == 0) ? bq : ((proj == 1) ? bk : bv);
    float sc = gg[o] * rsqrtf(var + 1e-5f);
    g_scale[proj][o] = sc;
    g_shift[proj][o] = be[o] - mean * sc;
}

// ---------------- Stage 3: fold BN+LeakyReLU from fp16 y ----------------
__global__ __launch_bounds__(256) void fold2_kernel()
{
    int p0 = blockIdx.x * 64, c0 = blockIdx.y * 64;
    int z = blockIdx.z, proj = z >> 3, b = z & 7;
    int tid = threadIdx.x;

    if (proj == 0) {
        for (int t = tid; t < 64 * 32; t += 256) {
            int c = c0 + (t >> 5), jp = (p0 >> 1) + (t & 31);
            float2 v = unpack2h(g_yh[0][b][c][jp]);
            float sc = g_scale[0][c], sh = g_shift[0][c];
            float v0 = v.x * sc + sh, v1 = v.y * sc + sh;
            v0 = (v0 >= 0.f) ? v0 : 0.1f * v0;
            v1 = (v1 >= 0.f) ? v1 : 0.1f * v1;
            g_Q[b][c][jp] = pack2h(v0, v1);
        }
        return;
    }

    __shared__ float sm[64][65];
    const float post = (proj == 1) ? K_ALPHA : 1.f;
    for (int t = tid; t < 64 * 32; t += 256) {
        int c = t >> 5, jp = t & 31;
        float2 v = unpack2h(g_yh[proj][b][c0 + c][(p0 >> 1) + jp]);
        float sc = g_scale[proj][c0 + c], sh = g_shift[proj][c0 + c];
        float v0 = v.x * sc + sh, v1 = v.y * sc + sh;
        v0 = ((v0 >= 0.f) ? v0 : 0.1f * v0) * post;
        v1 = ((v1 >= 0.f) ? v1 : 0.1f * v1) * post;
        sm[c][2 * jp] = v0;
        sm[c][2 * jp + 1] = v1;
    }
    __syncthreads();
    int h = c0 >> 7, cpo = (c0 & 127) >> 1;
    unsigned* dst = (proj == 1) ? &g_KT[0][0][0][0] : &g_VT[0][0][0][0];
    for (int t = tid; t < 64 * 32; t += 256) {
        int p = t >> 5, cp = t & 31;
        size_t o = ((size_t)(b * NH + h) * PP + p0 + p) * 64 + cpo + cp;
        dst[o] = pack2h(sm[2 * cp][p], sm[2 * cp + 1][p]);
    }
}

// ---------------- Stage 4: fp16 flash attention, 4-deep ring, paired sync -
// smem (u32): V 0 (4 bufs x 4352 = 17408)   [prologue stages K (8704) at 0]
//             Q 17408 (4 bufs x 4608 = 18432)
// V(j) in buf j&3; Q(j) in qbuf j&3. One barrier+wait+commit per TWO iters.
// Pair top (even jt): all warps past iter jt-1 => V(<=jt)/Q(<=jt-1) bufs dead;
// prefetch V(jt+3)->buf(jt+3)&3, V(jt+4)->buf jt&3, Q(jt+2), Q(jt+3).
#define OFF_V  0
#define OFF_Q  17408
#define ATTN10_SMEM ((17408 + 18432) * 4)

__global__ __launch_bounds__(256) void attn10_kernel(float* __restrict__ out)
{
    extern __shared__ unsigned sm[];
    uint32_t smb = (uint32_t)__cvta_generic_to_shared(sm);
    const int tid = threadIdx.x;
    const int w = tid >> 5, lane = tid & 31;
    const int g = lane >> 2, q = lane & 3;
    const int tt = lane >> 3, rr = lane & 7;
    const int bh = blockIdx.y, b = bh >> 3, h = bh & 7;
    const int i0 = blockIdx.x * 128;

    const unsigned* gK = &g_KT[b][h][0][0];
    const unsigned* gV = &g_VT[b][h][0][0];
    const unsigned* gQ = &g_Q[b][h * 128][0];

    const int aRow = 16 * w + (tt & 1) * 8 + rr;
    const int aCol = (tt >> 1) * 4;
    const int bRow0 = (tt & 1) * 8 + rr;

    // ---- prologue: stage K through smem (spans V bufs 0-1), extract ----
    for (int t = tid; t < 2048; t += 256) {
        int r = t >> 4, f4 = (t & 15) * 4;
        CP16(smb + 4 * (r * 68 + f4), gK + (size_t)(i0 + r) * 64 + f4);
    }
    CP_COMMIT();
    CP_WAIT(0);
    __syncthreads();

    unsigned kh[8][4];
    {
        const uint32_t kB = smb + 4 * (aRow * 68 + aCol);
#pragma unroll
        for (int ks = 0; ks < 8; ks++)
            LDSM4(kh[ks][0], kh[ks][1], kh[ks][2], kh[ks][3], kB + 32 * ks);
    }
    __syncthreads();

    // V(0) -> buf0 (own group, waited before prologue S(0))
    for (int t = tid; t < 1024; t += 256) {
        int r = t >> 4, f4 = (t & 15) * 4;
        CP16(smb + 4 * (OFF_V + r * 68 + f4), gV + (size_t)r * 64 + f4);
    }
    CP_COMMIT();
    // V(1)->buf1, V(2)->buf2, Q(0)->qbuf0, Q(1)->qbuf1 (one group)
    for (int t = tid; t < 2048; t += 256) {
        int j = 1 + (t >> 10);             // 1 or 2
        int r = (t >> 4) & 63, f4 = (t & 15) * 4;
        CP16(smb + 4 * (OFF_V + j * 4352 + r * 68 + f4),
             gV + (size_t)(j * 64 + r) * 64 + f4);
    }
    for (int t = tid; t < 2048; t += 256) {
        int jq = t >> 10;                  // 0 or 1
        int r = (t >> 3) & 127, f4 = (t & 7) * 4;
        CP16(smb + 4 * (OFF_Q + jq * 4608 + r * 36 + f4),
             gQ + (size_t)r * 1024 + jq * 32 + f4);
    }
    CP_COMMIT();

    float oacc[16][4];
#pragma unroll
    for (int nf = 0; nf < 16; nf++)
#pragma unroll
        for (int e = 0; e < 4; e++) oacc[nf][e] = 0.f;
    float l0 = 0.f, l1 = 0.f;
    float saccA[8][4], saccB[8][4];

    // ---- prologue S(0) -> saccA (V(0) resident after wait(1)) ----
    CP_WAIT(1);
    __syncthreads();
#pragma unroll
    for (int nf = 0; nf < 8; nf++)
#pragma unroll
        for (int e = 0; e < 4; e++) saccA[nf][e] = 0.f;
    {
        const uint32_t vBase = smb + 4 * (OFF_V + bRow0 * 68 + aCol);
#pragma unroll
        for (int ks = 0; ks < 8; ks++) {
#pragma unroll
            for (int nb = 0; nb < 4; nb++) {
                uint32_t vh0, vh1, vh2, vh3;
                LDSM4(vh0, vh1, vh2, vh3, vBase + 4 * (nb * 16 * 68) + 32 * ks);
                mma16816(saccA[2 * nb],     kh[ks][0], kh[ks][1], kh[ks][2], kh[ks][3], vh0, vh2);
                mma16816(saccA[2 * nb + 1], kh[ks][0], kh[ks][1], kh[ks][2], kh[ks][3], vh1, vh3);
            }
        }
    }

    // body: softmax(sO) -> P regs, S(jt+1)->sN, O^T(jt) += P*Q
#define ATTN_BODY(jt, sO, sN) do { \
        const int qb = (jt) & 3; \
        if ((jt) < 31) { \
            _Pragma("unroll") \
            for (int nf = 0; nf < 8; nf++) \
                _Pragma("unroll") \
                for (int e = 0; e < 4; e++) sN[nf][e] = 0.f; \
            const uint32_t vBase = smb + 4 * (OFF_V + (((jt) + 1) & 3) * 4352 + bRow0 * 68 + aCol); \
            _Pragma("unroll") \
            for (int ks = 0; ks < 8; ks++) { \
                _Pragma("unroll") \
                for (int nb = 0; nb < 4; nb++) { \
                    uint32_t vh0, vh1, vh2, vh3; \
                    LDSM4(vh0, vh1, vh2, vh3, vBase + 4 * (nb * 16 * 68) + 32 * ks); \
                    mma16816(sN[2 * nb],     kh[ks][0], kh[ks][1], kh[ks][2], kh[ks][3], vh0, vh2); \
                    mma16816(sN[2 * nb + 1], kh[ks][0], kh[ks][1], kh[ks][2], kh[ks][3], vh1, vh3); \
                } \
            } \
        } \
        unsigned pa[8], pb[8]; \
        _Pragma("unroll") \
        for (int nf = 0; nf < 8; nf++) { \
            float e0 = fex2(sO[nf][0]); \
            float e1 = fex2(sO[nf][1]); \
            float e2 = fex2(sO[nf][2]); \
            float e3 = fex2(sO[nf][3]); \
            l0 += e0 + e1; \
            l1 += e2 + e3; \
            pa[nf] = pack2h(e0, e1); \
            pb[nf] = pack2h(e2, e3); \
        } \
        const uint32_t qBase = smb + 4 * (OFF_Q + qb * 4608 + bRow0 * 36 + aCol); \
        _Pragma("unroll") \
        for (int ks = 0; ks < 4; ks++) { \
            _Pragma("unroll") \
            for (int cb = 0; cb < 8; cb++) { \
                uint32_t qh0, qh1, qh2, qh3; \
                LDSM4(qh0, qh1, qh2, qh3, qBase + 4 * (16 * cb * 36) + 32 * ks); \
                mma16816(oacc[2 * cb],     pa[2 * ks], pb[2 * ks], pa[2 * ks + 1], pb[2 * ks + 1], qh0, qh2); \
                mma16816(oacc[2 * cb + 1], pa[2 * ks], pb[2 * ks], pa[2 * ks + 1], pb[2 * ks + 1], qh1, qh3); \
            } \
        } \
    } while (0)

    for (int jt = 0; jt < 32; jt += 2) {
        CP_WAIT(0);
        __syncthreads();           // all warps past iter jt-1

        // prefetch for pair jt+2 (guarded); one commit group
        if (jt + 3 < 32) {
            const int jn = jt + 3;
            for (int t = tid; t < 1024; t += 256) {
                int r = t >> 4, f4 = (t & 15) * 4;
                CP16(smb + 4 * (OFF_V + (jn & 3) * 4352 + r * 68 + f4),
                     gV + (size_t)(jn * 64 + r) * 64 + f4);
            }
        }
        if (jt + 4 < 32) {
            const int jn = jt + 4;
            for (int t = tid; t < 1024; t += 256) {
                int r = t >> 4, f4 = (t & 15) * 4;
                CP16(smb + 4 * (OFF_V + (jn & 3) * 4352 + r * 68 + f4),
                     gV + (size_t)(jn * 64 + r) * 64 + f4);
            }
        }
        if (jt + 2 < 32) {
            const int jn = jt + 2;
            for (int t = tid; t < 1024; t += 256) {
                int r = t >> 3, f4 = (t & 7) * 4;
                CP16(smb + 4 * (OFF_Q + (jn & 3) * 4608 + r * 36 + f4),
                     gQ + (size_t)r * 1024 + jn * 32 + f4);
            }
        }
        if (jt + 3 < 32) {
            const int jn = jt + 3;
            for (int t = tid; t < 1024; t += 256) {
                int r = t >> 3, f4 = (t & 7) * 4;
                CP16(smb + 4 * (OFF_Q + (jn & 3) * 4608 + r * 36 + f4),
                     gQ + (size_t)r * 1024 + jn * 32 + f4);
            }
        }
        CP_COMMIT();

        ATTN_BODY(jt,     saccA, saccB);
        ATTN_BODY(jt + 1, saccB, saccA);
    }
#undef ATTN_BODY

    // ---- finalize: thread owns rows i = 16w+g (l0), 16w+g+8 (l1) ----
    l0 += __shfl_xor_sync(0xffffffffu, l0, 1);
    l0 += __shfl_xor_sync(0xffffffffu, l0, 2);
    l1 += __shfl_xor_sync(0xffffffffu, l1, 1);
    l1 += __shfl_xor_sync(0xffffffffu, l1, 2);
    float il0 = 1.f / l0, il1 = 1.f / l1;
    const int iA = i0 + 16 * w + g;
#pragma unroll
    for (int nf = 0; nf < 16; nf++) {
        int c = h * 128 + 8 * nf + 2 * q;
        float* r0 = out + ((size_t)b * COUT + c) * PP;
        float* r1 = out + ((size_t)b * COUT + c + 1) * PP;
        r0[iA] = oacc[nf][0] * il0;
        r1[iA] = oacc[nf][1] * il0;
        r0[iA + 8] = oacc[nf][2] * il1;
        r1[iA + 8] = oacc[nf][3] * il1;
    }
}

// ---------------------------------------------------------------------------
extern "C" void kernel_launch(void* const* d_in, const int* in_sizes, int n_in,
                              void* d_out, int out_size)
{
    const float* x  = (const float*)d_in[0];
    const float* Wq = (const float*)d_in[1];
    const float* gq = (const float*)d_in[2];
    const float* bq = (const float*)d_in[3];
    const float* Wk = (const float*)d_in[4];
    const float* gk = (const float*)d_in[5];
    const float* bk = (const float*)d_in[6];
    const float* Wv = (const float*)d_in[7];
    const float* gv = (const float*)d_in[8];
    const float* bv = (const float*)d_in[9];
    float* out = (float*)d_out;

    conv_w_kernel<<<3 * COUT * (CIN / 2) / 256, 256>>>(Wq, Wk, Wv);
    conv_x_kernel<<<dim3(PP / 64, CIN / 64, BB), 256>>>(x);

    cudaFuncSetAttribute(gemm1c_kernel, cudaFuncAttributeMaxDynamicSharedMemorySize, G2_SMEM);
    gemm1c_kernel<<<dim3(PP / 128, COUT / 128, 3 * BB), 256, G2_SMEM>>>();

    finalize_stats_kernel<<<12, 256>>>(gq, bq, gk, bk, gv, bv);
    fold2_kernel<<<dim3(PP / 64, COUT / 64, 3 * BB), 256>>>();

    cudaFuncSetAttribute(attn10_kernel, cudaFuncAttributeMaxDynamicSharedMemorySize, ATTN10_SMEM);
    attn10_kernel<<<dim3(PP / 128, BB * NH), 256, ATTN10_SMEM>>>(out);
}

// round 17
// speedup vs baseline: 1.0104x; 1.0104x over previous
#include <cuda_runtime.h>
#include <cuda_fp16.h>
#include <math.h>
#include <stdint.h>

#define BB 8
#define CIN 512
#define COUT 1024
#define PP 2048
#define NH 8
#define DH 128

// ---------------- scratch (device globals; no allocations) ----------------
__device__ unsigned g_yh[3][BB][COUT][PP/2];    // fp16 projections (pre-BN), pairs along p
__device__ float    g_sum[3][COUT];             // batch stats accumulators
__device__ float    g_sumsq[3][COUT];
__device__ unsigned g_W[3][COUT][CIN/2];        // W rounded fp16 pairs along c
__device__ unsigned g_XT[BB][PP][CIN/2];        // x^T rounded fp16 pairs
__device__ unsigned g_Q[BB][COUT][PP/2];        // Q rounded fp16 pairs along p
__device__ unsigned g_KT[BB][NH][PP][DH/2];     // K^T rounded (pre-scaled)
__device__ unsigned g_VT[BB][NH][PP][DH/2];     // V^T rounded fp16

// log2(e) / sqrt(128): folded into K so softmax is a bare ex2
#define K_ALPHA 0.12751743f

// ---------------- helpers ----------------
__device__ __forceinline__ unsigned pack2h(float x0, float x1) {
    unsigned h;
    asm("cvt.rn.f16x2.f32 %0, %1, %2;" : "=r"(h) : "f"(x1), "f"(x0));
    return h;
}
__device__ __forceinline__ float2 unpack2h(unsigned u) {
    __half2 h = *(__half2*)&u;
    return make_float2(__half2float(__low2half(h)), __half2float(__high2half(h)));
}
__device__ __forceinline__ float fex2(float x) {
    float y;
    asm("ex2.approx.ftz.f32 %0, %1;" : "=f"(y) : "f"(x));
    return y;
}
__device__ __forceinline__ void mma16816(float* c,
    unsigned a0, unsigned a1, unsigned a2, unsigned a3, unsigned b0, unsigned b1)
{
    asm volatile(
        "mma.sync.aligned.m16n8k16.row.col.f32.f16.f16.f32 "
        "{%0,%1,%2,%3}, {%4,%5,%6,%7}, {%8,%9}, {%0,%1,%2,%3};\n"
        : "+f"(c[0]), "+f"(c[1]), "+f"(c[2]), "+f"(c[3])
        : "r"(a0), "r"(a1), "r"(a2), "r"(a3), "r"(b0), "r"(b1));
}

#define CP16(d, s) asm volatile("cp.async.cg.shared.global [%0], [%1], 16;" :: "r"(d), "l"(s) : "memory")
#define CP_COMMIT() asm volatile("cp.async.commit_group;" ::: "memory")
#define CP_WAIT(n)  asm volatile("cp.async.wait_group %0;" :: "n"(n) : "memory")
#define LDSM4(r0, r1, r2, r3, a) \
    asm volatile("ldmatrix.sync.aligned.m8n8.x4.shared.b16 {%0,%1,%2,%3}, [%4];" \
        : "=r"(r0), "=r"(r1), "=r"(r2), "=r"(r3) : "r"(a))

// ---------------- prep: W -> fp16 pairs, x -> x^T fp16 pairs, zero stats ---
// blocks [0, 3072): W convert (+stats zero). blocks [3072, 5120): x^T convert.
__global__ __launch_bounds__(256) void prep_kernel(
    const float* __restrict__ x,
    const float* __restrict__ Wq, const float* __restrict__ Wk, const float* __restrict__ Wv)
{
    int bid = blockIdx.x;
    int tid = threadIdx.x;
    if (bid < 3072) {
        int idx = bid * 256 + tid;
        if (idx < 3 * COUT) {
            (&g_sum[0][0])[idx] = 0.f;
            (&g_sumsq[0][0])[idx] = 0.f;
        }
        int proj = idx >> 18;
        int rem = idx & 262143;
        const float* W = (proj == 0) ? Wq : ((proj == 1) ? Wk : Wv);
        float2 v = *(const float2*)(W + (size_t)rem * 2);
        (&g_W[0][0][0])[(size_t)proj * 262144 + rem] = pack2h(v.x, v.y);
        return;
    }
    __shared__ float sm[64][65];
    int b2 = bid - 3072;                      // 2048 blocks: 32 x 8 x 8
    int p0 = (b2 & 31) * 64;
    int c0 = ((b2 >> 5) & 7) * 64;
    int b = b2 >> 8;
    for (int t = tid; t < 64 * 64; t += 256) {
        int c = t >> 6, p = t & 63;
        sm[c][p] = x[((size_t)b * CIN + c0 + c) * PP + p0 + p];
    }
    __syncthreads();
    for (int t = tid; t < 64 * 32; t += 256) {
        int p = t >> 5, cp = t & 31;
        size_t o = ((size_t)b * PP + p0 + p) * 256 + (c0 >> 1) + cp;
        (&g_XT[0][0][0])[o] = pack2h(sm[2 * cp][p], sm[2 * cp + 1][p]);
    }
}

// ---------------- Stage 1: GEMM y = W*x, fp16 store + fused stats ---------
#define G2_STR 20
#define G2_STAGE 5120
#define G2_SMEM (2 * G2_STAGE * 4)

__global__ __launch_bounds__(256, 2) void gemm1c_kernel()
{
    extern __shared__ unsigned su[];
    uint32_t smb = (uint32_t)__cvta_generic_to_shared(su);
    int z = blockIdx.z, proj = z >> 3, b = z & 7;
    int o0 = blockIdx.y * 128, p0 = blockIdx.x * 128;
    const unsigned* gW = &g_W[proj][0][0];
    const unsigned* gX = &g_XT[b][0][0];
    const int tid = threadIdx.x, w = tid >> 5, lane = tid & 31;
    const int g = lane >> 2, q = lane & 3;
    const int tt = lane >> 3, rr = lane & 7;
    const int wo = w >> 2, wp = w & 3;

    float acc[4][4][4];
#pragma unroll
    for (int i = 0; i < 4; i++)
#pragma unroll
        for (int j = 0; j < 4; j++)
#pragma unroll
            for (int e = 0; e < 4; e++) acc[i][j][e] = 0.f;

#define G2_LOAD(c) do { \
        int _s = (c) & 1, _kk = (c) * 16; \
        uint32_t _sb = smb + 4 * (_s * G2_STAGE); \
        for (int t = tid; t < 512; t += 256) { \
            int r = t >> 2, f4 = (t & 3) * 4; \
            uint32_t d = _sb + 4 * (r * G2_STR + f4); \
            CP16(d,            gW + (size_t)(o0 + r) * 256 + _kk + f4); \
            CP16(d + 4 * 2560, gX + (size_t)(p0 + r) * 256 + _kk + f4); \
        } \
    } while (0)

    G2_LOAD(0);
    CP_COMMIT();

    const int fragRow = (tt & 1) * 8 + rr;
    const int fragCol = (tt >> 1) * 4;

    for (int c = 0; c < 16; c++) {
        if (c < 15) {
            G2_LOAD(c + 1);
            CP_COMMIT();
            CP_WAIT(1);
        } else {
            CP_WAIT(0);
        }
        __syncthreads();

        const int s = c & 1;
        const uint32_t aB = smb + 4 * (s * G2_STAGE + (wo * 64 + fragRow) * G2_STR + fragCol);
        const uint32_t bB = smb + 4 * (s * G2_STAGE + 2560 + (wp * 32 + fragRow) * G2_STR + fragCol);
#pragma unroll
        for (int ks = 0; ks < 2; ks++) {
            uint32_t a[4][4];
            uint32_t bh[2][4];
#pragma unroll
            for (int nb = 0; nb < 2; nb++) {
                uint32_t ba = bB + 4 * (16 * nb * G2_STR + 8 * ks);
                LDSM4(bh[nb][0], bh[nb][1], bh[nb][2], bh[nb][3], ba);
            }
#pragma unroll
            for (int mf = 0; mf < 4; mf++) {
                uint32_t aa = aB + 4 * (16 * mf * G2_STR + 8 * ks);
                LDSM4(a[mf][0], a[mf][1], a[mf][2], a[mf][3], aa);
            }
#pragma unroll
            for (int nb = 0; nb < 2; nb++)
#pragma unroll
                for (int mf = 0; mf < 4; mf++) {
                    mma16816(acc[mf][2 * nb],     a[mf][0], a[mf][1], a[mf][2], a[mf][3], bh[nb][0], bh[nb][2]);
                    mma16816(acc[mf][2 * nb + 1], a[mf][0], a[mf][1], a[mf][2], a[mf][3], bh[nb][1], bh[nb][3]);
                }
        }
        __syncthreads();
    }

    unsigned* Yh = &g_yh[proj][b][0][0];
    const int pp2 = (p0 >> 1) + wp * 16 + q;
#pragma unroll
    for (int mf = 0; mf < 4; mf++) {
        int oo = o0 + wo * 64 + 16 * mf + g;
#pragma unroll
        for (int nf = 0; nf < 4; nf++) {
            Yh[(size_t)oo * 1024 + pp2 + 4 * nf] = pack2h(acc[mf][nf][0], acc[mf][nf][1]);
            Yh[(size_t)(oo + 8) * 1024 + pp2 + 4 * nf] = pack2h(acc[mf][nf][2], acc[mf][nf][3]);
        }
    }
#pragma unroll
    for (int mf = 0; mf < 4; mf++) {
#pragma unroll
        for (int half = 0; half < 2; half++) {
            float s = 0.f, s2 = 0.f;
#pragma unroll
            for (int nf = 0; nf < 4; nf++) {
                float v0 = acc[mf][nf][2 * half], v1 = acc[mf][nf][2 * half + 1];
                s += v0 + v1;
                s2 += v0 * v0 + v1 * v1;
            }
            s += __shfl_xor_sync(0xffffffffu, s, 1);
            s += __shfl_xor_sync(0xffffffffu, s, 2);
            s2 += __shfl_xor_sync(0xffffffffu, s2, 1);
            s2 += __shfl_xor_sync(0xffffffffu, s2, 2);
            if (q == 0) {
                int o = o0 + wo * 64 + 16 * mf + g + 8 * half;
                atomicAdd(&g_sum[proj][o], s);
                atomicAdd(&g_sumsq[proj][o], s2);
            }
        }
    }
}

// ---------------- Stage 2: fold BN+LeakyReLU (inline stats finalize) ------
__global__ __launch_bounds__(256) void fold3_kernel(
    const float* __restrict__ gq, const float* __restrict__ bq,
    const float* __restrict__ gk, const float* __restrict__ bk,
    const float* __restrict__ gv, const float* __restrict__ bv)
{
    int p0 = blockIdx.x * 64, c0 = blockIdx.y * 64;
    int z = blockIdx.z, proj = z >> 3, b = z & 7;
    int tid = threadIdx.x;

    __shared__ float scs[64], shs[64];
    __shared__ float sm[64][65];

    if (tid < 64) {
        int o = c0 + tid;
        const float invn = 1.f / (BB * PP);
        float mean = g_sum[proj][o] * invn;
        float var = g_sumsq[proj][o] * invn - mean * mean;
        const float* gg = (proj == 0) ? gq : ((proj == 1) ? gk : gv);
        const float* be = (proj == 0) ? bq : ((proj == 1) ? bk : bv);
        float sc = gg[o] * rsqrtf(var + 1e-5f);
        scs[tid] = sc;
        shs[tid] = be[o] - mean * sc;
    }
    __syncthreads();

    if (proj == 0) {
        for (int t = tid; t < 64 * 32; t += 256) {
            int ci = t >> 5;
            int c = c0 + ci, jp = (p0 >> 1) + (t & 31);
            float2 v = unpack2h(g_yh[0][b][c][jp]);
            float sc = scs[ci], sh = shs[ci];
            float v0 = v.x * sc + sh, v1 = v.y * sc + sh;
            v0 = (v0 >= 0.f) ? v0 : 0.1f * v0;
            v1 = (v1 >= 0.f) ? v1 : 0.1f * v1;
            g_Q[b][c][jp] = pack2h(v0, v1);
        }
        return;
    }

    const float post = (proj == 1) ? K_ALPHA : 1.f;
    for (int t = tid; t < 64 * 32; t += 256) {
        int ci = t >> 5, jp = t & 31;
        float2 v = unpack2h(g_yh[proj][b][c0 + ci][(p0 >> 1) + jp]);
        float sc = scs[ci], sh = shs[ci];
        float v0 = v.x * sc + sh, v1 = v.y * sc + sh;
        v0 = ((v0 >= 0.f) ? v0 : 0.1f * v0) * post;
        v1 = ((v1 >= 0.f) ? v1 : 0.1f * v1) * post;
        sm[ci][2 * jp] = v0;
        sm[ci][2 * jp + 1] = v1;
    }
    __syncthreads();
    int h = c0 >> 7, cpo = (c0 & 127) >> 1;
    unsigned* dst = (proj == 1) ? &g_KT[0][0][0][0] : &g_VT[0][0][0][0];
    for (int t = tid; t < 64 * 32; t += 256) {
        int p = t >> 5, cp = t & 31;
        size_t o = ((size_t)(b * NH + h) * PP + p0 + p) * 64 + cpo + cp;
        dst[o] = pack2h(sm[2 * cp][p], sm[2 * cp + 1][p]);
    }
}

// ---------------- Stage 3: fp16 flash attention, P-in-registers -----------
// smem (u32): V 0 (2 bufs x 4352)   [prologue stages K (8704 u32) at 0]
//             Q 8704 (2 bufs x 4608)
// Iter jt: S(jt+1)->sacc_new, softmax(sacc_old)->P regs, O^T(jt) += P * Q.
#define OFF_V  0
#define OFF_Q  8704
#define ATTN9_SMEM ((8704 + 2 * 4608) * 4)

__global__ __launch_bounds__(256) void attn9_kernel(float* __restrict__ out)
{
    extern __shared__ unsigned sm[];
    uint32_t smb = (uint32_t)__cvta_generic_to_shared(sm);
    const int tid = threadIdx.x;
    const int w = tid >> 5, lane = tid & 31;
    const int g = lane >> 2, q = lane & 3;
    const int tt = lane >> 3, rr = lane & 7;
    const int bh = blockIdx.y, b = bh >> 3, h = bh & 7;
    const int i0 = blockIdx.x * 128;

    const unsigned* gK = &g_KT[b][h][0][0];
    const unsigned* gV = &g_VT[b][h][0][0];
    const unsigned* gQ = &g_Q[b][h * 128][0];

    const int aRow = 16 * w + (tt & 1) * 8 + rr;
    const int aCol = (tt >> 1) * 4;
    const int bRow0 = (tt & 1) * 8 + rr;

    // ---- prologue: stage K through smem, extract A-fragments to regs ----
    for (int t = tid; t < 2048; t += 256) {
        int r = t >> 4, f4 = (t & 15) * 4;
        CP16(smb + 4 * (r * 68 + f4), gK + (size_t)(i0 + r) * 64 + f4);
    }
    CP_COMMIT();
    CP_WAIT(0);
    __syncthreads();

    unsigned kh[8][4];
    {
        const uint32_t kB = smb + 4 * (aRow * 68 + aCol);
#pragma unroll
        for (int ks = 0; ks < 8; ks++)
            LDSM4(kh[ks][0], kh[ks][1], kh[ks][2], kh[ks][3], kB + 32 * ks);
    }
    __syncthreads();

    // V(0) -> buf0
    for (int t = tid; t < 1024; t += 256) {
        int r = t >> 4, f4 = (t & 15) * 4;
        CP16(smb + 4 * (OFF_V + r * 68 + f4), gV + (size_t)r * 64 + f4);
    }
    CP_COMMIT();
    // V(1) -> buf1, Q(0) -> qbuf0
    for (int t = tid; t < 1024; t += 256) {
        int r = t >> 4, f4 = (t & 15) * 4;
        CP16(smb + 4 * (OFF_V + 4352 + r * 68 + f4), gV + (size_t)(64 + r) * 64 + f4);
    }
    for (int t = tid; t < 1024; t += 256) {
        int r = t >> 3, f4 = (t & 7) * 4;
        CP16(smb + 4 * (OFF_Q + r * 36 + f4), gQ + (size_t)r * 1024 + f4);
    }
    CP_COMMIT();

    // O^T accumulators: oacc[nf] covers c = 8nf + {2q, 2q+1}, rows g / g+8
    float oacc[16][4];
#pragma unroll
    for (int nf = 0; nf < 16; nf++)
#pragma unroll
        for (int e = 0; e < 4; e++) oacc[nf][e] = 0.f;
    float l0 = 0.f, l1 = 0.f;
    float saccA[8][4], saccB[8][4];

    // ---- prologue S(0) -> saccA ----
    CP_WAIT(1);
    __syncthreads();
#pragma unroll
    for (int nf = 0; nf < 8; nf++)
#pragma unroll
        for (int e = 0; e < 4; e++) saccA[nf][e] = 0.f;
    {
        const uint32_t vBase = smb + 4 * (OFF_V + bRow0 * 68 + aCol);
#pragma unroll
        for (int ks = 0; ks < 8; ks++) {
#pragma unroll
            for (int nb = 0; nb < 4; nb++) {
                uint32_t vh0, vh1, vh2, vh3;
                LDSM4(vh0, vh1, vh2, vh3, vBase + 4 * (nb * 16 * 68) + 32 * ks);
                mma16816(saccA[2 * nb],     kh[ks][0], kh[ks][1], kh[ks][2], kh[ks][3], vh0, vh2);
                mma16816(saccA[2 * nb + 1], kh[ks][0], kh[ks][1], kh[ks][2], kh[ks][3], vh1, vh3);
            }
        }
    }

#define ATTN_ITER(jt, sO, sN) do { \
        const int qb = (jt) & 1; \
        CP_WAIT(0); \
        __syncthreads(); \
        if ((jt) < 30) { \
            const int jn2 = ((jt) + 2) * 64; \
            for (int t = tid; t < 1024; t += 256) { \
                int r = t >> 4, f4 = (t & 15) * 4; \
                CP16(smb + 4 * (OFF_V + qb * 4352 + r * 68 + f4), \
                     gV + (size_t)(jn2 + r) * 64 + f4); \
            } \
        } \
        if ((jt) < 31) { \
            const int jn = ((jt) + 1) * 64; \
            for (int t = tid; t < 1024; t += 256) { \
                int r = t >> 3, f4 = (t & 7) * 4; \
                CP16(smb + 4 * (OFF_Q + (qb ^ 1) * 4608 + r * 36 + f4), \
                     gQ + (size_t)r * 1024 + (jn >> 1) + f4); \
            } \
            CP_COMMIT(); \
        } \
        if ((jt) < 31) { \
            _Pragma("unroll") \
            for (int nf = 0; nf < 8; nf++) \
                _Pragma("unroll") \
                for (int e = 0; e < 4; e++) sN[nf][e] = 0.f; \
            const uint32_t vBase = smb + 4 * (OFF_V + (qb ^ 1) * 4352 + bRow0 * 68 + aCol); \
            _Pragma("unroll") \
            for (int ks = 0; ks < 8; ks++) { \
                _Pragma("unroll") \
                for (int nb = 0; nb < 4; nb++) { \
                    uint32_t vh0, vh1, vh2, vh3; \
                    LDSM4(vh0, vh1, vh2, vh3, vBase + 4 * (nb * 16 * 68) + 32 * ks); \
                    mma16816(sN[2 * nb],     kh[ks][0], kh[ks][1], kh[ks][2], kh[ks][3], vh0, vh2); \
                    mma16816(sN[2 * nb + 1], kh[ks][0], kh[ks][1], kh[ks][2], kh[ks][3], vh1, vh3); \
                } \
            } \
        } \
        unsigned pa[8], pb[8]; \
        _Pragma("unroll") \
        for (int nf = 0; nf < 8; nf++) { \
            float e0 = fex2(sO[nf][0]); \
            float e1 = fex2(sO[nf][1]); \
            float e2 = fex2(sO[nf][2]); \
            float e3 = fex2(sO[nf][3]); \
            l0 += e0 + e1; \
            l1 += e2 + e3; \
            pa[nf] = pack2h(e0, e1); \
            pb[nf] = pack2h(e2, e3); \
        } \
        const uint32_t qBase = smb + 4 * (OFF_Q + qb * 4608 + bRow0 * 36 + aCol); \
        _Pragma("unroll") \
        for (int ks = 0; ks < 4; ks++) { \
            _Pragma("unroll") \
            for (int cb = 0; cb < 8; cb++) { \
                uint32_t qh0, qh1, qh2, qh3; \
                LDSM4(qh0, qh1, qh2, qh3, qBase + 4 * (16 * cb * 36) + 32 * ks); \
                mma16816(oacc[2 * cb],     pa[2 * ks], pb[2 * ks], pa[2 * ks + 1], pb[2 * ks + 1], qh0, qh2); \
                mma16816(oacc[2 * cb + 1], pa[2 * ks], pb[2 * ks], pa[2 * ks + 1], pb[2 * ks + 1], qh1, qh3); \
            } \
        } \
    } while (0)

    for (int jt = 0; jt < 32; jt += 2) {
        ATTN_ITER(jt,     saccA, saccB);
        ATTN_ITER(jt + 1, saccB, saccA);
    }
#undef ATTN_ITER

    // ---- finalize: thread owns exactly rows i = 16w+g (l0), 16w+g+8 (l1) ----
    l0 += __shfl_xor_sync(0xffffffffu, l0, 1);
    l0 += __shfl_xor_sync(0xffffffffu, l0, 2);
    l1 += __shfl_xor_sync(0xffffffffu, l1, 1);
    l1 += __shfl_xor_sync(0xffffffffu, l1, 2);
    float il0 = 1.f / l0, il1 = 1.f / l1;
    const int iA = i0 + 16 * w + g;
#pragma unroll
    for (int nf = 0; nf < 16; nf++) {
        int c = h * 128 + 8 * nf + 2 * q;
        float* r0 = out + ((size_t)b * COUT + c) * PP;
        float* r1 = out + ((size_t)b * COUT + c + 1) * PP;
        r0[iA] = oacc[nf][0] * il0;
        r1[iA] = oacc[nf][1] * il0;
        r0[iA + 8] = oacc[nf][2] * il1;
        r1[iA + 8] = oacc[nf][3] * il1;
    }
}

// ---------------------------------------------------------------------------
extern "C" void kernel_launch(void* const* d_in, const int* in_sizes, int n_in,
                              void* d_out, int out_size)
{
    const float* x  = (const float*)d_in[0];
    const float* Wq = (const float*)d_in[1];
    const float* gq = (const float*)d_in[2];
    const float* bq = (const float*)d_in[3];
    const float* Wk = (const float*)d_in[4];
    const float* gk = (const float*)d_in[5];
    const float* bk = (const float*)d_in[6];
    const float* Wv = (const float*)d_in[7];
    const float* gv = (const float*)d_in[8];
    const float* bv = (const float*)d_in[9];
    float* out = (float*)d_out;

    prep_kernel<<<5120, 256>>>(x, Wq, Wk, Wv);

    cudaFuncSetAttribute(gemm1c_kernel, cudaFuncAttributeMaxDynamicSharedMemorySize, G2_SMEM);
    gemm1c_kernel<<<dim3(PP / 128, COUT / 128, 3 * BB), 256, G2_SMEM>>>();

    fold3_kernel<<<dim3(PP / 64, COUT / 64, 3 * BB), 256>>>(gq, bq, gk, bk, gv, bv);

    cudaFuncSetAttribute(attn9_kernel, cudaFuncAttributeMaxDynamicSharedMemorySize, ATTN9_SMEM);
    attn9_kernel<<<dim3(PP / 128, BB * NH), 256, ATTN9_SMEM>>>(out);
}